// round 7
// baseline (speedup 1.0000x reference)
#include <cuda_runtime.h>
#include <cstdint>

#define IN_DIM  128
#define OUT_DIM 128
#define NHEADS  4
#define NEG_SLOPE 0.2f

#define N_MAX 50000
#define E_MAX 1600000
#define FULL 0xFFFFFFFFu
#define MAXC 4
#define PROJ_NPB 32
#define HIST_BLOCKS 1024

// -------- device scratch (static: no allocation allowed) --------
__device__ float g_hq   [N_MAX * NHEADS];
__device__ float g_kact [N_MAX * NHEADS];
__device__ float g_qagg [N_MAX * NHEADS];
__device__ float g_hproj[(size_t)N_MAX * OUT_DIM];
__device__ int   g_cnt  [N_MAX];   // zeroed at load; re-zeroed by scan_kernel each run
__device__ int   g_off  [N_MAX + 1];
__device__ int   g_pos  [N_MAX];
__device__ int   g_csr_col[E_MAX];

// ===== fused kernel: projections (first blocks) + row histogram (rest) =====
__global__ __launch_bounds__(256) void proj_hist_kernel(
    const float* __restrict__ x,
    const float* __restrict__ Wq, const float* __restrict__ Wk,
    const float* __restrict__ Wl, const float* __restrict__ bl,
    const int* __restrict__ rows,
    int N, int E, int proj_blocks)
{
    const int t = threadIdx.x;
    if ((int)blockIdx.x >= proj_blocks) {
        // ---------- histogram part (grid-stride over edges) ----------
        int start = ((int)blockIdx.x - proj_blocks) * 256 + t;
        int stride = HIST_BLOCKS * 256;
        for (int e = start; e < E; e += stride)
            atomicAdd(&g_cnt[__ldg(rows + e)], 1);
        return;
    }

    // ---------- projection part: 32 nodes per block ----------
    __shared__ float xs[PROJ_NPB * IN_DIM];   // 16 KB
    const int base = blockIdx.x * PROJ_NPB;
    const int nn = min(PROJ_NPB, N - base);
    if (nn <= 0) return;

    {
        const float4* xg = (const float4*)(x + (size_t)base * IN_DIM);
        float4* xs4 = (float4*)xs;
        const int tot4 = nn * (IN_DIM / 4);
        for (int i = t; i < tot4; i += 256) xs4[i] = xg[i];
    }
    __syncthreads();

    const int half = t >> 7;          // 0 or 1: which 16-node group
    const int tl   = t & 127;         // owns output column tl
    const int hbase = half * 16;      // node offset within tile
    const int hn = min(16, nn - hbase);

    // per-head q/k projections: tl = n2*8 + h
    {
        const int n2 = tl >> 3;
        const int h  = tl & 7;
        if (n2 < hn) {
            const float* wrow = (h < 4) ? (Wq + h * IN_DIM) : (Wk + (h - 4) * IN_DIM);
            const float4* w4 = (const float4*)wrow;
            const float4* xr = (const float4*)(xs + (hbase + n2) * IN_DIM);
            float d = 0.0f;
            #pragma unroll
            for (int k = 0; k < IN_DIM / 4; k++) {
                float4 w = w4[k]; float4 xv = xr[k];
                d += w.x * xv.x + w.y * xv.y + w.z * xv.z + w.w * xv.w;
            }
            const int node = base + hbase + n2;
            if (h < 4) g_hq[node * NHEADS + h] = d;
            else       g_kact[node * NHEADS + (h - 4)] = (d >= 0.0f) ? d : NEG_SLOPE * d;
        }
    }

    if (hn <= 0) return;
    float acc[16];
    #pragma unroll
    for (int n = 0; n < 16; n++) acc[n] = 0.0f;

    const float4* wl4 = (const float4*)(Wl + (size_t)tl * IN_DIM);
    const float4* xh  = (const float4*)(xs + hbase * IN_DIM);
    #pragma unroll 4
    for (int k = 0; k < IN_DIM / 4; k++) {
        float4 w = wl4[k];
        #pragma unroll
        for (int n = 0; n < 16; n++) {
            float4 xv = xh[n * (IN_DIM / 4) + k];
            acc[n] += w.x * xv.x + w.y * xv.y + w.z * xv.z + w.w * xv.w;
        }
    }
    const float b = bl[tl];
    for (int n = 0; n < hn; n++)
        g_hproj[(size_t)(base + hbase + n) * OUT_DIM + tl] = acc[n] + b;
}

// ================= single-block scan (also re-zeros g_cnt) ============
__device__ __forceinline__ int warp_incl_scan(int v, int lane) {
    #pragma unroll
    for (int d = 1; d < 32; d <<= 1) {
        int t = __shfl_up_sync(FULL, v, d);
        if (lane >= d) v += t;
    }
    return v;
}

__global__ __launch_bounds__(1024) void scan_kernel(int N, int E) {
    const int tid = threadIdx.x;
    const int lane = tid & 31, wid = tid >> 5;
    __shared__ int wtot[32];
    int carry = 0;
    for (int base = 0; base < N; base += 1024) {
        int i = base + tid;
        int v = 0;
        if (i < N) { v = g_cnt[i]; g_cnt[i] = 0; }
        int s = warp_incl_scan(v, lane);
        if (lane == 31) wtot[wid] = s;
        __syncthreads();
        if (wid == 0) {
            int ws = wtot[lane];
            #pragma unroll
            for (int d = 1; d < 32; d <<= 1) {
                int t = __shfl_up_sync(FULL, ws, d);
                if (lane >= d) ws += t;
            }
            wtot[lane] = ws;
        }
        __syncthreads();
        int excl = carry + (wid ? wtot[wid - 1] : 0) + s - v;
        if (i < N) { g_off[i] = excl; g_pos[i] = excl; }
        int tot = wtot[31];
        __syncthreads();
        carry += tot;
    }
    if (tid == 0) g_off[N] = E;
}

// ================= kernel: scatter edges into CSR =================
__global__ __launch_bounds__(256) void scatter_kernel(
    const int* __restrict__ rows, const int* __restrict__ cols, int E)
{
    int e = blockIdx.x * 256 + threadIdx.x;
    if (e >= E) return;
    int r = rows[e];
    int p = atomicAdd(&g_pos[r], 1);
    g_csr_col[p] = cols[e];
}

// ================= kernel: q_agg via CSR (no atomics) =================
__global__ __launch_bounds__(256) void qagg_csr_kernel(int N) {
    int w = (blockIdx.x * 256 + threadIdx.x) >> 5;
    int lane = threadIdx.x & 31;
    if (w >= N) return;
    int beg = g_off[w], end = g_off[w + 1];
    float4 acc = {0.f, 0.f, 0.f, 0.f};
    for (int e = beg + lane; e < end; e += 32) {
        int c = __ldg(g_csr_col + e);
        float4 v = __ldg(((const float4*)g_hq) + c);
        acc.x += v.x; acc.y += v.y; acc.z += v.z; acc.w += v.w;
    }
    #pragma unroll
    for (int d = 16; d; d >>= 1) {
        acc.x += __shfl_xor_sync(FULL, acc.x, d);
        acc.y += __shfl_xor_sync(FULL, acc.y, d);
        acc.z += __shfl_xor_sync(FULL, acc.z, d);
        acc.w += __shfl_xor_sync(FULL, acc.w, d);
    }
    if (lane == 0) ((float4*)g_qagg)[w] = acc;
}

// ================= fused attention + aggregation (warp per node) ======
__device__ __forceinline__ void agg_strip(float4& acc, float a, int c, int lane, int cnt) {
    #pragma unroll 8
    for (int j = 0; j < 32; j++) {
        if (j >= cnt) break;
        float aj = __shfl_sync(FULL, a, j);
        int   cj = __shfl_sync(FULL, c, j);
        float4 v = __ldg(((const float4*)g_hproj) + (size_t)cj * (OUT_DIM / 4) + lane);
        acc.x = fmaf(aj, v.x, acc.x);
        acc.y = fmaf(aj, v.y, acc.y);
        acc.z = fmaf(aj, v.z, acc.z);
        acc.w = fmaf(aj, v.w, acc.w);
    }
}

__global__ __launch_bounds__(256) void attn_agg_kernel(float* __restrict__ out, int N) {
    int node = (blockIdx.x * 256 + threadIdx.x) >> 5;
    int lane = threadIdx.x & 31;
    if (node >= N) return;
    const int beg = g_off[node], end = g_off[node + 1];
    const int deg = end - beg;

    float4* outp = ((float4*)out) + (size_t)node * (OUT_DIM / 4) + lane;
    if (deg == 0) { float4 z = {0.f,0.f,0.f,0.f}; *outp = z; return; }

    const float4 ka = ((const float4*)g_kact)[node];
    float4 acc = {0.f, 0.f, 0.f, 0.f};

    // pass 1: per-head max
    float4 mx = {-3.4e38f, -3.4e38f, -3.4e38f, -3.4e38f};
    for (int e = beg + lane; e < end; e += 32) {
        int c = __ldg(g_csr_col + e);
        float4 q = __ldg(((const float4*)g_qagg) + c);
        mx.x = fmaxf(mx.x, ka.x * q.x);
        mx.y = fmaxf(mx.y, ka.y * q.y);
        mx.z = fmaxf(mx.z, ka.z * q.z);
        mx.w = fmaxf(mx.w, ka.w * q.w);
    }
    #pragma unroll
    for (int d = 16; d; d >>= 1) {
        mx.x = fmaxf(mx.x, __shfl_xor_sync(FULL, mx.x, d));
        mx.y = fmaxf(mx.y, __shfl_xor_sync(FULL, mx.y, d));
        mx.z = fmaxf(mx.z, __shfl_xor_sync(FULL, mx.z, d));
        mx.w = fmaxf(mx.w, __shfl_xor_sync(FULL, mx.w, d));
    }

    // pass 2: per-head sum of exp
    float4 sm = {0.f, 0.f, 0.f, 0.f};
    for (int e = beg + lane; e < end; e += 32) {
        int c = __ldg(g_csr_col + e);
        float4 q = __ldg(((const float4*)g_qagg) + c);
        sm.x += __expf(ka.x * q.x - mx.x);
        sm.y += __expf(ka.y * q.y - mx.y);
        sm.z += __expf(ka.z * q.z - mx.z);
        sm.w += __expf(ka.w * q.w - mx.w);
    }
    #pragma unroll
    for (int d = 16; d; d >>= 1) {
        sm.x += __shfl_xor_sync(FULL, sm.x, d);
        sm.y += __shfl_xor_sync(FULL, sm.y, d);
        sm.z += __shfl_xor_sync(FULL, sm.z, d);
        sm.w += __shfl_xor_sync(FULL, sm.w, d);
    }
    float4 inv;
    inv.x = 0.25f * __fdividef(1.0f, sm.x + 1e-8f);
    inv.y = 0.25f * __fdividef(1.0f, sm.y + 1e-8f);
    inv.z = 0.25f * __fdividef(1.0f, sm.z + 1e-8f);
    inv.w = 0.25f * __fdividef(1.0f, sm.w + 1e-8f);

    // pass 3: alpha per edge strip, broadcast + accumulate
    for (int base = beg; base < end; base += 32) {
        int e = base + lane;
        float a = 0.0f; int c = 0;
        if (e < end) {
            c = __ldg(g_csr_col + e);
            float4 q = __ldg(((const float4*)g_qagg) + c);
            a = __expf(ka.x * q.x - mx.x) * inv.x
              + __expf(ka.y * q.y - mx.y) * inv.y
              + __expf(ka.z * q.z - mx.z) * inv.z
              + __expf(ka.w * q.w - mx.w) * inv.w;
        }
        agg_strip(acc, a, c, lane, min(32, end - base));
    }

    // fused final leaky relu + single coalesced write
    acc.x = (acc.x >= 0.f) ? acc.x : NEG_SLOPE * acc.x;
    acc.y = (acc.y >= 0.f) ? acc.y : NEG_SLOPE * acc.y;
    acc.z = (acc.z >= 0.f) ? acc.z : NEG_SLOPE * acc.z;
    acc.w = (acc.w >= 0.f) ? acc.w : NEG_SLOPE * acc.w;
    *outp = acc;
}

// ================= launch =================
extern "C" void kernel_launch(void* const* d_in, const int* in_sizes, int n_in,
                              void* d_out, int out_size)
{
    const float* x  = (const float*)d_in[0];
    const int*   ei = (const int*)d_in[1];
    const float* Wq = (const float*)d_in[2];
    const float* Wk = (const float*)d_in[3];
    const float* Wl = (const float*)d_in[4];
    const float* bl = (const float*)d_in[5];
    float* out = (float*)d_out;

    const int N = in_sizes[0] / IN_DIM;
    const int E = in_sizes[1] / 2;
    const int* rows = ei;
    const int* cols = ei + E;

    const int proj_blocks = (N + PROJ_NPB - 1) / PROJ_NPB;

    // 1: projections + histogram fused in one launch (hist hides under proj)
    proj_hist_kernel<<<proj_blocks + HIST_BLOCKS, 256>>>(
        x, Wq, Wk, Wl, bl, rows, N, E, proj_blocks);
    // 2: offsets (single block; also re-zeros g_cnt for next replay)
    scan_kernel<<<1, 1024>>>(N, E);
    // 3: scatter edges into CSR
    scatter_kernel<<<(E + 255) / 256, 256>>>(rows, cols, E);
    // 4: q aggregation (no atomics)
    qagg_csr_kernel<<<(N * 32 + 255) / 256, 256>>>(N);
    // 5: fused softmax + weighted aggregation + leaky
    attn_agg_kernel<<<(N * 32 + 255) / 256, 256>>>(out, N);
}

// round 8
// speedup vs baseline: 1.1241x; 1.1241x over previous
#include <cuda_runtime.h>
#include <cstdint>

#define IN_DIM  128
#define OUT_DIM 128
#define NHEADS  4
#define NEG_SLOPE 0.2f

#define N_MAX 50000
#define E_MAX 1600000
#define FULL 0xFFFFFFFFu

// -------- device scratch (static: no allocation allowed) --------
__device__ float g_hq   [N_MAX * NHEADS];
__device__ float g_kact [N_MAX * NHEADS];
__device__ float g_qagg [N_MAX * NHEADS];
__device__ float g_hproj[(size_t)N_MAX * OUT_DIM];
__device__ int   g_cnt  [N_MAX];
__device__ int   g_off  [N_MAX + 1];
__device__ int   g_pos  [N_MAX];
__device__ int   g_bsum [256];
__device__ int   g_csr_col[E_MAX];

// ================= kernel 0: init (zero histogram) =================
__global__ __launch_bounds__(256) void init_kernel(int N) {
    int i = blockIdx.x * 256 + threadIdx.x;
    if (i < N) g_cnt[i] = 0;
}

// ================= kernel 1: projections =================
#define NPB 16
__global__ __launch_bounds__(128) void proj_kernel(
    const float* __restrict__ x,
    const float* __restrict__ Wq, const float* __restrict__ Wk,
    const float* __restrict__ Wl, const float* __restrict__ bl, int N)
{
    __shared__ float xs[NPB * IN_DIM];
    const int t = threadIdx.x;
    const int base = blockIdx.x * NPB;
    const int nn = min(NPB, N - base);
    if (nn <= 0) return;

    {
        const float4* xg = (const float4*)(x + (size_t)base * IN_DIM);
        float4* xs4 = (float4*)xs;
        const int tot4 = nn * (IN_DIM / 4);
        for (int i = t; i < tot4; i += 128) xs4[i] = xg[i];
    }
    __syncthreads();

    // per-head q/k projections: t = n2*8 + h
    {
        const int n2 = t >> 3;
        const int h  = t & 7;
        if (n2 < nn) {
            const float* wrow = (h < 4) ? (Wq + h * IN_DIM) : (Wk + (h - 4) * IN_DIM);
            const float4* w4 = (const float4*)wrow;
            const float4* xr = (const float4*)(xs + n2 * IN_DIM);
            float d = 0.0f;
            #pragma unroll
            for (int k = 0; k < IN_DIM / 4; k++) {
                float4 w = w4[k]; float4 xv = xr[k];
                d += w.x * xv.x + w.y * xv.y + w.z * xv.z + w.w * xv.w;
            }
            const int node = base + n2;
            if (h < 4) g_hq[node * NHEADS + h] = d;
            else       g_kact[node * NHEADS + (h - 4)] = (d >= 0.0f) ? d : NEG_SLOPE * d;
        }
    }

    float acc[NPB];
    #pragma unroll
    for (int n = 0; n < NPB; n++) acc[n] = 0.0f;

    const float4* wl4 = (const float4*)(Wl + (size_t)t * IN_DIM);
    #pragma unroll 4
    for (int k = 0; k < IN_DIM / 4; k++) {
        float4 w = wl4[k];
        #pragma unroll
        for (int n = 0; n < NPB; n++) {
            float4 xv = ((const float4*)(xs + n * IN_DIM))[k];
            acc[n] += w.x * xv.x + w.y * xv.y + w.z * xv.z + w.w * xv.w;
        }
    }
    const float b = bl[t];
    for (int n = 0; n < nn; n++)
        g_hproj[(size_t)(base + n) * OUT_DIM + t] = acc[n] + b;
}

// ================= kernel 2: histogram of rows =================
__global__ __launch_bounds__(256) void hist_kernel(const int* __restrict__ rows, int E) {
    int e = blockIdx.x * 256 + threadIdx.x;
    if (e < E) atomicAdd(&g_cnt[rows[e]], 1);
}

// ================= scan (3 stages) =================
__device__ __forceinline__ int warp_incl_scan(int v, int lane) {
    #pragma unroll
    for (int d = 1; d < 32; d <<= 1) {
        int t = __shfl_up_sync(FULL, v, d);
        if (lane >= d) v += t;
    }
    return v;
}

__global__ __launch_bounds__(256) void scan1_kernel(int N) {
    int i = blockIdx.x * 256 + threadIdx.x;
    int lane = threadIdx.x & 31, wid = threadIdx.x >> 5;
    int v = (i < N) ? g_cnt[i] : 0;
    int s = warp_incl_scan(v, lane);
    __shared__ int wsum[8];
    if (lane == 31) wsum[wid] = s;
    __syncthreads();
    if (wid == 0) {
        int ws = (lane < 8) ? wsum[lane] : 0;
        #pragma unroll
        for (int d = 1; d < 8; d <<= 1) {
            int t = __shfl_up_sync(FULL, ws, d);
            if (lane >= d) ws += t;
        }
        if (lane < 8) wsum[lane] = ws;
    }
    __syncthreads();
    int excl = s - v + (wid > 0 ? wsum[wid - 1] : 0);
    if (i < N) g_off[i] = excl;
    if (threadIdx.x == 255) g_bsum[blockIdx.x] = excl + v;
}

__global__ __launch_bounds__(256) void scan2_kernel(int nb) {
    int i = threadIdx.x;
    int lane = i & 31, wid = i >> 5;
    int v = (i < nb) ? g_bsum[i] : 0;
    int s = warp_incl_scan(v, lane);
    __shared__ int wsum[8];
    if (lane == 31) wsum[wid] = s;
    __syncthreads();
    if (wid == 0) {
        int ws = (lane < 8) ? wsum[lane] : 0;
        #pragma unroll
        for (int d = 1; d < 8; d <<= 1) {
            int t = __shfl_up_sync(FULL, ws, d);
            if (lane >= d) ws += t;
        }
        if (lane < 8) wsum[lane] = ws;
    }
    __syncthreads();
    int excl = s - v + (wid > 0 ? wsum[wid - 1] : 0);
    if (i < nb) g_bsum[i] = excl;
}

__global__ __launch_bounds__(256) void scan3_kernel(int N, int E) {
    int i = blockIdx.x * 256 + threadIdx.x;
    if (i < N) {
        int o = g_off[i] + g_bsum[i >> 8];
        g_off[i] = o;
        g_pos[i] = o;
    }
    if (i == 0) g_off[N] = E;
}

// ================= kernel: scatter edges into CSR =================
__global__ __launch_bounds__(256) void scatter_kernel(
    const int* __restrict__ rows, const int* __restrict__ cols, int E)
{
    int e = blockIdx.x * 256 + threadIdx.x;
    if (e >= E) return;
    int r = rows[e];
    int p = atomicAdd(&g_pos[r], 1);
    g_csr_col[p] = cols[e];
}

// ================= kernel: q_agg via CSR (no atomics) =================
__global__ __launch_bounds__(256) void qagg_csr_kernel(int N) {
    int w = (blockIdx.x * 256 + threadIdx.x) >> 5;
    int lane = threadIdx.x & 31;
    if (w >= N) return;
    int beg = g_off[w], end = g_off[w + 1];
    float4 acc = {0.f, 0.f, 0.f, 0.f};
    for (int e = beg + lane; e < end; e += 32) {
        int c = __ldg(g_csr_col + e);
        float4 v = __ldg(((const float4*)g_hq) + c);
        acc.x += v.x; acc.y += v.y; acc.z += v.z; acc.w += v.w;
    }
    #pragma unroll
    for (int d = 16; d; d >>= 1) {
        acc.x += __shfl_xor_sync(FULL, acc.x, d);
        acc.y += __shfl_xor_sync(FULL, acc.y, d);
        acc.z += __shfl_xor_sync(FULL, acc.z, d);
        acc.w += __shfl_xor_sync(FULL, acc.w, d);
    }
    if (lane == 0) ((float4*)g_qagg)[w] = acc;
}

// ================= fused attention + aggregation (warp per node) ======
// Fully unrolled strip: no data-dependent break. Invalid lanes carry a=0,c=0
// so the extra FMAs add zero; removing the break lets ptxas front-batch the
// shfl+LDG pairs (high MLP) instead of serializing on each L2 gather.
__device__ __forceinline__ void agg_strip(float4& acc, float a, int c, int lane) {
    #pragma unroll
    for (int j = 0; j < 32; j++) {
        float aj = __shfl_sync(FULL, a, j);
        int   cj = __shfl_sync(FULL, c, j);
        float4 v = __ldg(((const float4*)g_hproj) + (size_t)cj * (OUT_DIM / 4) + lane);
        acc.x = fmaf(aj, v.x, acc.x);
        acc.y = fmaf(aj, v.y, acc.y);
        acc.z = fmaf(aj, v.z, acc.z);
        acc.w = fmaf(aj, v.w, acc.w);
    }
}

__global__ __launch_bounds__(256) void attn_agg_kernel(float* __restrict__ out, int N) {
    int node = (blockIdx.x * 256 + threadIdx.x) >> 5;
    int lane = threadIdx.x & 31;
    if (node >= N) return;
    const int beg = g_off[node], end = g_off[node + 1];
    const int deg = end - beg;

    float4* outp = ((float4*)out) + (size_t)node * (OUT_DIM / 4) + lane;
    if (deg == 0) { float4 z = {0.f,0.f,0.f,0.f}; *outp = z; return; }

    const float4 ka = ((const float4*)g_kact)[node];
    float4 acc = {0.f, 0.f, 0.f, 0.f};

    // pass 1: per-head max
    float4 mx = {-3.4e38f, -3.4e38f, -3.4e38f, -3.4e38f};
    for (int e = beg + lane; e < end; e += 32) {
        int c = __ldg(g_csr_col + e);
        float4 q = __ldg(((const float4*)g_qagg) + c);
        mx.x = fmaxf(mx.x, ka.x * q.x);
        mx.y = fmaxf(mx.y, ka.y * q.y);
        mx.z = fmaxf(mx.z, ka.z * q.z);
        mx.w = fmaxf(mx.w, ka.w * q.w);
    }
    #pragma unroll
    for (int d = 16; d; d >>= 1) {
        mx.x = fmaxf(mx.x, __shfl_xor_sync(FULL, mx.x, d));
        mx.y = fmaxf(mx.y, __shfl_xor_sync(FULL, mx.y, d));
        mx.z = fmaxf(mx.z, __shfl_xor_sync(FULL, mx.z, d));
        mx.w = fmaxf(mx.w, __shfl_xor_sync(FULL, mx.w, d));
    }

    // pass 2: per-head sum of exp
    float4 sm = {0.f, 0.f, 0.f, 0.f};
    for (int e = beg + lane; e < end; e += 32) {
        int c = __ldg(g_csr_col + e);
        float4 q = __ldg(((const float4*)g_qagg) + c);
        sm.x += __expf(ka.x * q.x - mx.x);
        sm.y += __expf(ka.y * q.y - mx.y);
        sm.z += __expf(ka.z * q.z - mx.z);
        sm.w += __expf(ka.w * q.w - mx.w);
    }
    #pragma unroll
    for (int d = 16; d; d >>= 1) {
        sm.x += __shfl_xor_sync(FULL, sm.x, d);
        sm.y += __shfl_xor_sync(FULL, sm.y, d);
        sm.z += __shfl_xor_sync(FULL, sm.z, d);
        sm.w += __shfl_xor_sync(FULL, sm.w, d);
    }
    float4 inv;
    inv.x = 0.25f * __fdividef(1.0f, sm.x + 1e-8f);
    inv.y = 0.25f * __fdividef(1.0f, sm.y + 1e-8f);
    inv.z = 0.25f * __fdividef(1.0f, sm.z + 1e-8f);
    inv.w = 0.25f * __fdividef(1.0f, sm.w + 1e-8f);

    // pass 3: alpha per edge strip, broadcast + accumulate (no break)
    for (int base = beg; base < end; base += 32) {
        int e = base + lane;
        float a = 0.0f; int c = 0;
        if (e < end) {
            c = __ldg(g_csr_col + e);
            float4 q = __ldg(((const float4*)g_qagg) + c);
            a = __expf(ka.x * q.x - mx.x) * inv.x
              + __expf(ka.y * q.y - mx.y) * inv.y
              + __expf(ka.z * q.z - mx.z) * inv.z
              + __expf(ka.w * q.w - mx.w) * inv.w;
        }
        agg_strip(acc, a, c, lane);
    }

    // fused final leaky relu + single coalesced write
    acc.x = (acc.x >= 0.f) ? acc.x : NEG_SLOPE * acc.x;
    acc.y = (acc.y >= 0.f) ? acc.y : NEG_SLOPE * acc.y;
    acc.z = (acc.z >= 0.f) ? acc.z : NEG_SLOPE * acc.z;
    acc.w = (acc.w >= 0.f) ? acc.w : NEG_SLOPE * acc.w;
    *outp = acc;
}

// ================= launch =================
extern "C" void kernel_launch(void* const* d_in, const int* in_sizes, int n_in,
                              void* d_out, int out_size)
{
    const float* x  = (const float*)d_in[0];
    const int*   ei = (const int*)d_in[1];
    const float* Wq = (const float*)d_in[2];
    const float* Wk = (const float*)d_in[3];
    const float* Wl = (const float*)d_in[4];
    const float* bl = (const float*)d_in[5];
    float* out = (float*)d_out;

    const int N = in_sizes[0] / IN_DIM;
    const int E = in_sizes[1] / 2;
    const int* rows = ei;
    const int* cols = ei + E;
    const int nblocksN = (N + 255) / 256;

    init_kernel<<<nblocksN, 256>>>(N);
    proj_kernel<<<(N + NPB - 1) / NPB, 128>>>(x, Wq, Wk, Wl, bl, N);
    hist_kernel<<<(E + 255) / 256, 256>>>(rows, E);
    scan1_kernel<<<nblocksN, 256>>>(N);
    scan2_kernel<<<1, 256>>>(nblocksN);
    scan3_kernel<<<nblocksN, 256>>>(N, E);
    scatter_kernel<<<(E + 255) / 256, 256>>>(rows, cols, E);
    qagg_csr_kernel<<<(N * 32 + 255) / 256, 256>>>(N);
    attn_agg_kernel<<<(N * 32 + 255) / 256, 256>>>(out, N);
}